// round 10
// baseline (speedup 1.0000x reference)
#include <cuda_runtime.h>

#define EPSF 1e-9f
#define FMINN 1.17549435e-38f
#define TOPKK 13
#define MAXB 8
#define MAXN 50
#define MAXL 8400
#define MAXK 17

extern "C" __device__ float __nv_expf(float);
extern "C" __device__ float __nv_powf(float, float);

__device__ float g_align[MAXB*MAXN*MAXL];
__device__ float g_iou  [MAXB*MAXN*MAXL];
__device__ unsigned char g_mask[MAXB*MAXN*MAXL]; // bit0=in_gts, bit1=in_topk
__device__ short g_coln[MAXB*MAXL];
__device__ unsigned char g_pos[MAXB*MAXL];
__device__ float g_maxm [MAXB*MAXN];
__device__ float g_maxi [MAXB*MAXN];

__device__ __forceinline__ float ftz(float x) { return (x < FMINN) ? 0.f : x; }

// ============================================================
// K1: pairwise metrics, FTZ pipeline (XLA GPU ftz semantics)
// ============================================================
__global__ void __launch_bounds__(256)
k1_metrics(const float* __restrict__ ps, const float* __restrict__ pb,
           const float* __restrict__ pp, const float* __restrict__ ap,
           const int*   __restrict__ glab, const float* __restrict__ gb,
           const float* __restrict__ gp, const float* __restrict__ sg,
           int B, int L, int C, int N, int K)
{
    __shared__ float4 s_box[MAXN];
    __shared__ float4 s_kp [MAXN*MAXK];   // gx, gy, screen-thresh, vis
    __shared__ float2 s_misc[MAXN];       // clipped area, num_vis+eps
    __shared__ float  s_aeps[MAXN];       // w*h*0.53 + EPS
    __shared__ float  s_s2[MAXK];         // (2*sigma)^2
    __shared__ int    s_lab[MAXN];

    const int b = blockIdx.y;
    const int tid = threadIdx.x;

    if (tid < K) {
        float t = __fmul_rn(2.0f, sg[tid]);
        s_s2[tid] = __fmul_rn(t, t);
    }
    for (int n = tid; n < N; n += blockDim.x) {
        float4 bx = ((const float4*)gb)[b*N + n];
        s_box[n] = bx;
        float wg = __fsub_rn(bx.z, bx.x), hg = __fsub_rn(bx.w, bx.y);
        s_misc[n].x = __fmul_rn(fmaxf(wg, 0.f), fmaxf(hg, 0.f));
        s_aeps[n] = __fadd_rn(__fmul_rn(__fmul_rn(wg, hg), 0.53f), EPSF);
        s_lab[n] = glab[b*N + n];
    }
    __syncthreads();
    for (int j = tid; j < N*MAXK; j += blockDim.x) {
        int n = j / MAXK, k = j - n*MAXK;
        const float* g = gp + ((long)(b*N + n)*MAXK + k)*3;
        // d > th  =>  e > 87.9  =>  exp term < min-normal => flushed to 0
        double th = (double)s_s2[k] * (double)s_aeps[n] * 2.0 * 87.9;
        s_kp[j] = make_float4(g[0], g[1], (float)th, (g[2] > 0.f) ? 1.f : 0.f);
    }
    __syncthreads();
    for (int n = tid; n < N; n += blockDim.x) {
        float c = 0.f;
        #pragma unroll
        for (int k = 0; k < MAXK; k++) c = __fadd_rn(c, s_kp[n*MAXK + k].w);
        s_misc[n].y = __fadd_rn(c, EPSF);
    }
    __syncthreads();

    const int l = blockIdx.x*blockDim.x + tid;
    if (l >= L) return;

    float4 p = ((const float4*)pb)[b*L + l];
    float area_p = __fmul_rn(fmaxf(__fsub_rn(p.z, p.x), 0.f),
                             fmaxf(__fsub_rn(p.w, p.y), 0.f));
    float axx = ap[l*2], ayy = ap[l*2 + 1];

    float2 kp[MAXK];
    const float2* pprow = (const float2*)(pp + ((long)(b*L + l))*MAXK*2);
    #pragma unroll
    for (int k = 0; k < MAXK; k++) kp[k] = pprow[k];
    const float* psrow = ps + (long)(b*L + l)*C;

    const long base = ((long)b*N)*L + l;
    for (int n = 0; n < N; n++) {
        float4 g4 = s_box[n];
        float ox = __fsub_rn(fminf(g4.z, p.z), fmaxf(g4.x, p.x));
        float oy = __fsub_rn(fminf(g4.w, p.w), fmaxf(g4.y, p.y));
        float ov = __fmul_rn(fmaxf(ox, 0.f), fmaxf(oy, 0.f));
        float dmin = fminf(fminf(__fsub_rn(axx, g4.x), __fsub_rn(ayy, g4.y)),
                           fminf(__fsub_rn(g4.z, axx), __fsub_rn(g4.w, ayy)));
        float io2 = 0.f, al = 0.f;
        if (ov > 0.f) {
            float2 mi = s_misc[n];
            float den = __fadd_rn(__fsub_rn(__fadd_rn(mi.x, area_p), ov), EPSF);
            float iou = __fdiv_rn(ov, den);
            float aeps = s_aeps[n];
            float s = 0.f;
            #pragma unroll
            for (int k = 0; k < MAXK; k++) {
                float4 kk = s_kp[n*MAXK + k];
                if (kk.w > 0.f) {
                    float dx = __fsub_rn(kk.x, kp[k].x);
                    float dy = __fsub_rn(kk.y, kp[k].y);
                    float d  = __fadd_rn(__fmul_rn(dx, dx), __fmul_rn(dy, dy));
                    if (d <= kk.z) {
                        float e = __fdiv_rn(__fdiv_rn(__fdiv_rn(d, s_s2[k]), aeps), 2.0f);
                        s = __fadd_rn(s, ftz(__nv_expf(-e)));   // ftz exp
                    }
                }
            }
            float oks = ftz(__fdiv_rn(s, mi.y));                // ftz div
            io2 = ftz(__fmul_rn(iou, oks));                     // ftz mul
            float p6 = ftz(__nv_powf(io2, 6.0f));               // ftz pow
            al = ftz(__fmul_rn(psrow[s_lab[n]], p6));           // ftz mul
        }
        long idx = base + (long)n*L;
        g_iou[idx]   = io2;
        g_align[idx] = al;
        g_mask[idx]  = (dmin > EPSF) ? 1 : 0;
    }
}

// ============================================================
// K2: top-13 per (b,n); ties: value desc, index ASC (lowest)
// ============================================================
__global__ void __launch_bounds__(256)
k2_topk(const float* __restrict__ pad, int B, int L, int N)
{
    __shared__ float sval[MAXL];
    __shared__ float rv[256];
    __shared__ int   ri[256];
    __shared__ int   ssel[TOPKK];

    const int n = blockIdx.x, b = blockIdx.y;
    const int tid = threadIdx.x;
    const long row = ((long)(b*N + n))*L;

    if (tid == 0) { g_maxm[b*N + n] = 0.f; g_maxi[b*N + n] = 0.f; }
    if (pad[b*N + n] <= 0.f) return;

    for (int i = tid; i < L; i += blockDim.x)
        sval[i] = (g_mask[row + i] & 1) ? g_align[row + i] : 0.f;
    __syncthreads();

    for (int t = 0; t < TOPKK; t++) {
        float bv = -1.f; int bi = 0x7fffffff;
        for (int i = tid; i < L; i += blockDim.x) {
            float v = sval[i];
            if (v > bv) { bv = v; bi = i; }   // ascending scan keeps lowest idx on ties
        }
        rv[tid] = bv; ri[tid] = bi;
        __syncthreads();
        for (int off = blockDim.x >> 1; off > 0; off >>= 1) {
            if (tid < off) {
                float v2 = rv[tid+off]; int i2 = ri[tid+off];
                if (v2 > rv[tid] || (v2 == rv[tid] && i2 < ri[tid])) { rv[tid] = v2; ri[tid] = i2; }
            }
            __syncthreads();
        }
        if (tid == 0) { ssel[t] = ri[0]; sval[ri[0]] = -1.f; }
        __syncthreads();
    }
    if (tid < TOPKK) g_mask[row + ssel[tid]] |= 2;
}

// ============================================================
// K3: per-anchor resolve + per-gt max accumulation
// ============================================================
__global__ void __launch_bounds__(256)
k3_resolve(int B, int L, int N)
{
    const int l = blockIdx.x*blockDim.x + threadIdx.x;
    const int b = blockIdx.y;
    if (l >= L) return;
    const long base = ((long)b*N)*L + l;

    int cnt = 0, first = -1;
    for (int n = 0; n < N; n++) {
        if (g_mask[base + (long)n*L] == 3) { cnt++; if (first < 0) first = n; }
    }
    int asg = 0, pos = 0;
    if (cnt == 1) { asg = first; pos = 1; }
    else if (cnt > 1) {
        float bv = -3.402823e38f; int bi = 0;
        for (int n = 0; n < N; n++) {
            float v = g_iou[base + (long)n*L];
            if (v > bv) { bv = v; bi = n; }
        }
        asg = bi; pos = 1;
    }
    g_coln[b*L + l] = (short)asg;
    g_pos [b*L + l] = (unsigned char)pos;
    if (pos) {
        long idx = base + (long)asg*L;
        atomicMax((int*)&g_maxm[b*N + asg], __float_as_int(g_align[idx]));
        atomicMax((int*)&g_maxi[b*N + asg], __float_as_int(g_iou[idx]));
    }
}

// ============================================================
// K5: scalar outputs + bboxes
// layout: [labels BL][bboxes 4BL][poses 3K*BL][scores C*BL][gtidx BL][crowd BL]
// ============================================================
__global__ void __launch_bounds__(256)
k5_out(float* __restrict__ out,
       const int* __restrict__ glab, const float* __restrict__ gb,
       const int* __restrict__ gcrowd, const int* __restrict__ bgp,
       int B, int L, int C, int N, int K)
{
    const int l = blockIdx.x*blockDim.x + threadIdx.x;
    const int b = blockIdx.y;
    if (l >= L) return;
    const int bg = bgp ? bgp[0] : 1;

    const int n   = g_coln[b*L + l];
    const int pos = g_pos [b*L + l];
    const int crowd = gcrowd[b*N + n];

    const int lab_pre = pos ? glab[b*N + n] : bg;
    const int lab_fin = (crowd > 0) ? bg : lab_pre;

    float mult = 0.f;
    if (pos) {
        long idx = ((long)(b*N + n))*L + l;
        mult = __fmul_rn(__fdiv_rn(g_align[idx], __fadd_rn(g_maxm[b*N + n], EPSF)),
                         g_maxi[b*N + n]);
    }
    const float cf = (crowd < 1) ? 1.f : 0.f;

    const long BL = (long)B*L;
    const long o  = (long)b*L + l;

    out[o] = (float)lab_fin;
    ((float4*)(out + BL))[o] = ((const float4*)gb)[b*N + n];

    const long off_sc = BL*5 + BL*(long)K*3;
    for (int c = 0; c < C; c++) {
        int kept = (c < bg) ? c : c + 1;
        out[off_sc + o*C + c] = __fmul_rn((lab_pre == kept) ? mult : 0.f, cf);
    }
    const long off_gi = off_sc + BL*(long)C;
    out[off_gi + o]      = (float)(n + b*N);
    out[off_gi + BL + o] = (crowd > 0) ? 1.f : 0.f;
}

// ============================================================
// K6: pose gather, coalesced
// ============================================================
__global__ void __launch_bounds__(256)
k6_poses(float* __restrict__ out, const float* __restrict__ gp,
         int B, int L, int N, int K)
{
    const long total = (long)B*L*K*3;
    const long i = (long)blockIdx.x*blockDim.x + threadIdx.x;
    if (i >= total) return;
    const int K3 = K*3;
    const long bl = i / K3;
    const int  j  = (int)(i - bl*K3);
    const int  b  = (int)(bl / L);
    const int  n  = g_coln[bl];
    const long off = (long)B*L*5;
    out[off + i] = gp[((long)(b*N + n))*K3 + j];
}

extern "C" void kernel_launch(void* const* d_in, const int* in_sizes, int n_in,
                              void* d_out, int out_size)
{
    const float* ps   = (const float*)d_in[0];
    const float* pb   = (const float*)d_in[1];
    const float* pp   = (const float*)d_in[2];
    const float* ap   = (const float*)d_in[3];
    const int*   glab = (const int*)  d_in[4];
    const float* gb   = (const float*)d_in[5];
    const float* gp   = (const float*)d_in[6];
    const int*   gc   = (const int*)  d_in[7];
    const float* pad  = (const float*)d_in[8];
    const float* sg   = (const float*)d_in[9];
    const int*   bgp  = (n_in > 10) ? (const int*)d_in[10] : nullptr;

    const int K  = in_sizes[9];
    const int L  = in_sizes[3] / 2;
    const int BL = in_sizes[1] / 4;
    const int B  = BL / L;
    const int C  = in_sizes[0] / BL;
    const int N  = in_sizes[4] / B;

    dim3 blk(256);
    dim3 g1((L + 255)/256, B);
    k1_metrics<<<g1, blk>>>(ps, pb, pp, ap, glab, gb, gp, sg, B, L, C, N, K);
    k2_topk   <<<dim3(N, B), blk>>>(pad, B, L, N);
    k3_resolve<<<g1, blk>>>(B, L, N);
    k5_out    <<<g1, blk>>>((float*)d_out, glab, gb, gc, bgp, B, L, C, N, K);
    const long tot = (long)B*L*K*3;
    k6_poses  <<<(unsigned)((tot + 255)/256), blk>>>((float*)d_out, gp, B, L, N, K);
    (void)out_size;
}

// round 11
// speedup vs baseline: 1.2123x; 1.2123x over previous
#include <cuda_runtime.h>

#define EPSF 1e-9f
#define FMINN 1.17549435e-38f
#define TOPKK 13
#define MAXB 8
#define MAXN 50
#define MAXL 8400
#define MAXK 17
#define CH   25     // gts per K1 z-chunk
#define NCH  2
#define CAP  4096

extern "C" __device__ float __nv_expf(float);
extern "C" __device__ float __nv_powf(float, float);

// ---------------- device scratch ----------------
__device__ float g_align[MAXB*MAXN*MAXL];
__device__ float g_iou  [MAXB*MAXN*MAXL];
__device__ unsigned int       g_gts[NCH][MAXB*MAXL];   // in_gts bits (CH per word)
__device__ unsigned long long g_topk[MAXB*MAXL];       // topk bit n
__device__ short         g_coln[MAXB*MAXL];
__device__ unsigned char g_pos [MAXB*MAXL];
__device__ float g_maxm[MAXB*MAXN];
__device__ float g_maxi[MAXB*MAXN];
// K0 per-(b,n[,k]) precompute
__device__ float4 g_kp4 [MAXB*MAXN*MAXK];              // gx, gy, screen-thresh, vis
__device__ float  g_aeps[MAXB*MAXN];                   // w*h*0.53 + EPS
__device__ float  g_areac[MAXB*MAXN];                  // clipped area
__device__ float  g_nvise[MAXB*MAXN];                  // num_vis + EPS

__device__ __forceinline__ float ftz(float x) { return (x < FMINN) ? 0.f : x; }

// ============================================================
// K0: per-gt setup (hoisted out of K1)
// ============================================================
__global__ void __launch_bounds__(256)
k0_setup(const float* __restrict__ gb, const float* __restrict__ gp,
         const float* __restrict__ sg, int B, int N, int K)
{
    __shared__ float s_s2[MAXK];
    __shared__ float s_aeps[MAXN];
    const int b = blockIdx.x, tid = threadIdx.x;

    if (tid < K) { float t = __fmul_rn(2.0f, sg[tid]); s_s2[tid] = __fmul_rn(t, t); }
    if (tid < N) {
        int n = tid;
        const float* bx = gb + (b*N + n)*4;
        float wg = __fsub_rn(bx[2], bx[0]), hg = __fsub_rn(bx[3], bx[1]);
        g_areac[b*N + n] = __fmul_rn(fmaxf(wg, 0.f), fmaxf(hg, 0.f));
        float ae = __fadd_rn(__fmul_rn(__fmul_rn(wg, hg), 0.53f), EPSF);
        s_aeps[n] = ae; g_aeps[b*N + n] = ae;
        float c = 0.f;
        for (int k = 0; k < K; k++) {
            float v = gp[((long)(b*N + n)*K + k)*3 + 2];
            c = __fadd_rn(c, (v > 0.f) ? 1.f : 0.f);
        }
        g_nvise[b*N + n] = __fadd_rn(c, EPSF);
    }
    __syncthreads();
    for (int j = tid; j < N*K; j += blockDim.x) {
        int n = j / K, k = j - n*K;
        const float* g = gp + ((long)(b*N + n)*K + k)*3;
        // d > th  =>  e > 87.9  =>  exp term < min-normal => flushed to 0
        double th = (double)s_s2[k] * (double)s_aeps[n] * 2.0 * 87.9;
        g_kp4[(b*N + n)*K + k] = make_float4(g[0], g[1], (float)th, (g[2] > 0.f) ? 1.f : 0.f);
    }
}

// ============================================================
// K1: pairwise metrics, FTZ pipeline; z-chunked over gts
// ============================================================
__global__ void __launch_bounds__(256)
k1_metrics(const float* __restrict__ ps, const float* __restrict__ pb,
           const float* __restrict__ pp, const float* __restrict__ ap,
           const int*   __restrict__ glab, const float* __restrict__ gb,
           const float* __restrict__ sg,
           int B, int L, int C, int N, int K)
{
    __shared__ float4 s_box[CH];
    __shared__ float4 s_kp [CH*MAXK];
    __shared__ float  s_aeps[CH], s_areac[CH], s_nvise[CH];
    __shared__ int    s_lab[CH];
    __shared__ float  s_s2[MAXK];

    const int b = blockIdx.y, z = blockIdx.z, tid = threadIdx.x;
    const int c0 = z*CH;
    const int c1 = min(N, c0 + CH);
    const int cn = c1 - c0;

    if (tid < K) { float t = __fmul_rn(2.0f, sg[tid]); s_s2[tid] = __fmul_rn(t, t); }
    if (tid < cn) {
        int n = c0 + tid;
        s_box[tid]   = ((const float4*)gb)[b*N + n];
        s_aeps[tid]  = g_aeps[b*N + n];
        s_areac[tid] = g_areac[b*N + n];
        s_nvise[tid] = g_nvise[b*N + n];
        s_lab[tid]   = glab[b*N + n];
    }
    for (int j = tid; j < cn*K; j += blockDim.x)
        s_kp[j] = g_kp4[(b*N + c0)*K + j];
    __syncthreads();

    const int l = blockIdx.x*blockDim.x + tid;
    if (l >= L) return;

    float4 p = ((const float4*)pb)[b*L + l];
    float area_p = __fmul_rn(fmaxf(__fsub_rn(p.z, p.x), 0.f),
                             fmaxf(__fsub_rn(p.w, p.y), 0.f));
    float axx = ap[l*2], ayy = ap[l*2 + 1];

    float2 kp[MAXK];
    const float2* pprow = (const float2*)(pp + ((long)(b*L + l))*MAXK*2);
    #pragma unroll
    for (int k = 0; k < MAXK; k++) kp[k] = pprow[k];
    const float* psrow = ps + (long)(b*L + l)*C;

    unsigned int bits = 0;
    for (int j = 0; j < cn; j++) {
        const int n = c0 + j;
        float4 g4 = s_box[j];
        float ox = __fsub_rn(fminf(g4.z, p.z), fmaxf(g4.x, p.x));
        float oy = __fsub_rn(fminf(g4.w, p.w), fmaxf(g4.y, p.y));
        float ov = __fmul_rn(fmaxf(ox, 0.f), fmaxf(oy, 0.f));
        float dmin = fminf(fminf(__fsub_rn(axx, g4.x), __fsub_rn(ayy, g4.y)),
                           fminf(__fsub_rn(g4.z, axx), __fsub_rn(g4.w, ayy)));
        float io2 = 0.f, al = 0.f;
        if (ov > 0.f) {
            float den = __fadd_rn(__fsub_rn(__fadd_rn(s_areac[j], area_p), ov), EPSF);
            float iou = __fdiv_rn(ov, den);
            float aeps = s_aeps[j];
            float s = 0.f;
            #pragma unroll
            for (int k = 0; k < MAXK; k++) {
                float4 kk = s_kp[j*MAXK + k];
                if (kk.w > 0.f) {
                    float dx = __fsub_rn(kk.x, kp[k].x);
                    float dy = __fsub_rn(kk.y, kp[k].y);
                    float d  = __fadd_rn(__fmul_rn(dx, dx), __fmul_rn(dy, dy));
                    if (d <= kk.z) {
                        float e = __fdiv_rn(__fdiv_rn(__fdiv_rn(d, s_s2[k]), aeps), 2.0f);
                        s = __fadd_rn(s, ftz(__nv_expf(-e)));
                    }
                }
            }
            float oks = ftz(__fdiv_rn(s, s_nvise[j]));
            io2 = ftz(__fmul_rn(iou, oks));
            float p6 = ftz(__nv_powf(io2, 6.0f));
            al = ftz(__fmul_rn(psrow[s_lab[j]], p6));
        }
        long idx = ((long)(b*N + n))*L + l;
        g_iou[idx]   = io2;
        g_align[idx] = al;
        if (dmin > EPSF) bits |= (1u << j);
    }
    g_gts[z][b*L + l] = bits;
    if (z == 0) g_topk[b*L + l] = 0ull;   // reset per replay
}

// ============================================================
// K2: top-13 per (b,n) via candidate collection.
// candidates = {l : align>0 && in_gts}; rest of row is exact 0.
// top-13 = top candidates (val desc, idx asc) + lowest-index zero fill.
// ============================================================
__global__ void __launch_bounds__(256)
k2_topk(const float* __restrict__ pad, int B, int L, int N)
{
    __shared__ float cv[CAP];
    __shared__ int   ci[CAP];
    __shared__ int   cnt;
    __shared__ float rv[256];
    __shared__ int   ri[256];
    __shared__ int   rp[256];

    const int n = blockIdx.x, b = blockIdx.y, tid = threadIdx.x;
    const long row = ((long)(b*N + n))*L;

    if (tid == 0) { g_maxm[b*N + n] = 0.f; g_maxi[b*N + n] = 0.f; cnt = 0; }
    __syncthreads();
    if (pad[b*N + n] <= 0.f) return;

    const int zc = n / CH;
    const unsigned int bit = 1u << (n - zc*CH);
    for (int i = tid; i < L; i += 256) {
        float v = g_align[row + i];
        if (v > 0.f) {
            if (g_gts[zc][b*L + i] & bit) {
                int id = atomicAdd(&cnt, 1);
                if (id < CAP) { cv[id] = v; ci[id] = i; }
            }
        }
    }
    __syncthreads();

    const int c = min(cnt, CAP);
    const unsigned long long nb = 1ull << n;

    if (c <= TOPKK) {
        if (tid < c) atomicOr(&g_topk[(long)b*L + ci[tid]], nb);
        if (tid == 0) {
            int fill = TOPKK - c;
            for (int i = 0; fill > 0; i++) {
                bool cand = false;
                for (int j = 0; j < c; j++) if (ci[j] == i) { cand = true; break; }
                if (!cand) { atomicOr(&g_topk[(long)b*L + i], nb); fill--; }
            }
        }
    } else {
        for (int t = 0; t < TOPKK; t++) {
            float bv = -1.f; int ba = 0x7fffffff; int bp = -1;
            for (int i = tid; i < c; i += 256) {
                float v = cv[i]; int a = ci[i];
                if (v > bv || (v == bv && a < ba)) { bv = v; ba = a; bp = i; }
            }
            rv[tid] = bv; ri[tid] = ba; rp[tid] = bp;
            __syncthreads();
            for (int off = 128; off > 0; off >>= 1) {
                if (tid < off) {
                    float v2 = rv[tid+off]; int a2 = ri[tid+off];
                    if (v2 > rv[tid] || (v2 == rv[tid] && a2 < ri[tid])) {
                        rv[tid] = v2; ri[tid] = a2; rp[tid] = rp[tid+off];
                    }
                }
                __syncthreads();
            }
            if (tid == 0) {
                atomicOr(&g_topk[(long)b*L + ri[0]], nb);
                cv[rp[0]] = -1.f;
            }
            __syncthreads();
        }
    }
}

// ============================================================
// K3: per-anchor resolve via bit ops + per-gt max accumulation
// ============================================================
__global__ void __launch_bounds__(256)
k3_resolve(int B, int L, int N)
{
    const int l = blockIdx.x*blockDim.x + threadIdx.x;
    const int b = blockIdx.y;
    if (l >= L) return;
    const int bl = b*L + l;
    const long base = ((long)b*N)*L + l;

    unsigned long long gts = (unsigned long long)g_gts[0][bl]
                           | ((unsigned long long)g_gts[1][bl] << CH);
    unsigned long long pos64 = gts & g_topk[bl];
    int cnt = __popcll(pos64);

    int asg = 0, pos = 0;
    if (cnt == 1) { asg = __ffsll((long long)pos64) - 1; pos = 1; }
    else if (cnt > 1) {           // argmax_n ious, first-occurrence ties
        float bv = -3.402823e38f; int bi = 0;
        for (int n = 0; n < N; n++) {
            float v = g_iou[base + (long)n*L];
            if (v > bv) { bv = v; bi = n; }
        }
        asg = bi; pos = 1;
    }
    g_coln[bl] = (short)asg;
    g_pos [bl] = (unsigned char)pos;
    if (pos) {
        long idx = base + (long)asg*L;
        atomicMax((int*)&g_maxm[b*N + asg], __float_as_int(g_align[idx]));
        atomicMax((int*)&g_maxi[b*N + asg], __float_as_int(g_iou[idx]));
    }
}

// ============================================================
// K5: scalar outputs + bboxes (gt tables staged in smem)
// layout: [labels BL][bboxes 4BL][poses 3K*BL][scores C*BL][gtidx BL][crowd BL]
// ============================================================
__global__ void __launch_bounds__(256)
k5_out(float* __restrict__ out,
       const int* __restrict__ glab, const float* __restrict__ gb,
       const int* __restrict__ gcrowd, const int* __restrict__ bgp,
       int B, int L, int C, int N, int K)
{
    __shared__ int    s_lab[MAXN], s_crowd[MAXN];
    __shared__ float4 s_box[MAXN];
    __shared__ float  s_mm[MAXN], s_mi[MAXN];

    const int b = blockIdx.y, tid = threadIdx.x;
    if (tid < N) {
        s_lab[tid]   = glab[b*N + tid];
        s_crowd[tid] = gcrowd[b*N + tid];
        s_box[tid]   = ((const float4*)gb)[b*N + tid];
        s_mm[tid]    = g_maxm[b*N + tid];
        s_mi[tid]    = g_maxi[b*N + tid];
    }
    __syncthreads();

    const int l = blockIdx.x*blockDim.x + tid;
    if (l >= L) return;
    const int bg = bgp ? bgp[0] : 1;

    const int n     = g_coln[b*L + l];
    const int pos   = g_pos [b*L + l];
    const int crowd = s_crowd[n];

    const int lab_pre = pos ? s_lab[n] : bg;
    const int lab_fin = (crowd > 0) ? bg : lab_pre;

    float mult = 0.f;
    if (pos) {
        long idx = ((long)(b*N + n))*L + l;
        mult = __fmul_rn(__fdiv_rn(g_align[idx], __fadd_rn(s_mm[n], EPSF)), s_mi[n]);
    }
    const float cf = (crowd < 1) ? 1.f : 0.f;

    const long BL = (long)B*L;
    const long o  = (long)b*L + l;

    out[o] = (float)lab_fin;
    ((float4*)(out + BL))[o] = s_box[n];

    const long off_sc = BL*5 + BL*(long)K*3;
    for (int cc = 0; cc < C; cc++) {
        int kept = (cc < bg) ? cc : cc + 1;
        out[off_sc + o*C + cc] = __fmul_rn((lab_pre == kept) ? mult : 0.f, cf);
    }
    const long off_gi = off_sc + BL*(long)C;
    out[off_gi + o]      = (float)(n + b*N);
    out[off_gi + BL + o] = (crowd > 0) ? 1.f : 0.f;
}

// ============================================================
// K6: pose gather — gt poses staged in smem, coalesced writes
// ============================================================
__global__ void __launch_bounds__(256)
k6_poses(float* __restrict__ out, const float* __restrict__ gp,
         int B, int L, int N, int K)
{
    __shared__ float s_gp[MAXN*MAXK*3];
    const int b = blockIdx.y, tid = threadIdx.x;
    const int K3 = K*3;
    for (int j = tid; j < N*K3; j += 256) s_gp[j] = gp[(long)b*N*K3 + j];
    __syncthreads();

    const long i = (long)blockIdx.x*256 + tid;
    if (i >= (long)L*K3) return;
    const int l = (int)(i / K3);
    const int j = (int)(i - (long)l*K3);
    const int n = g_coln[b*L + l];
    out[(long)B*L*5 + (long)b*L*K3 + i] = s_gp[n*K3 + j];
}

// ============================================================
extern "C" void kernel_launch(void* const* d_in, const int* in_sizes, int n_in,
                              void* d_out, int out_size)
{
    const float* ps   = (const float*)d_in[0];
    const float* pb   = (const float*)d_in[1];
    const float* pp   = (const float*)d_in[2];
    const float* ap   = (const float*)d_in[3];
    const int*   glab = (const int*)  d_in[4];
    const float* gb   = (const float*)d_in[5];
    const float* gp   = (const float*)d_in[6];
    const int*   gc   = (const int*)  d_in[7];
    const float* pad  = (const float*)d_in[8];
    const float* sg   = (const float*)d_in[9];
    const int*   bgp  = (n_in > 10) ? (const int*)d_in[10] : nullptr;

    const int K  = in_sizes[9];
    const int L  = in_sizes[3] / 2;
    const int BL = in_sizes[1] / 4;
    const int B  = BL / L;
    const int C  = in_sizes[0] / BL;
    const int N  = in_sizes[4] / B;

    dim3 blk(256);
    const int gx = (L + 255)/256;
    k0_setup  <<<B, blk>>>(gb, gp, sg, B, N, K);
    k1_metrics<<<dim3(gx, B, NCH), blk>>>(ps, pb, pp, ap, glab, gb, sg, B, L, C, N, K);
    k2_topk   <<<dim3(N, B), blk>>>(pad, B, L, N);
    k3_resolve<<<dim3(gx, B), blk>>>(B, L, N);
    k5_out    <<<dim3(gx, B), blk>>>((float*)d_out, glab, gb, gc, bgp, B, L, C, N, K);
    const long tot = (long)L*K*3;
    k6_poses  <<<dim3((unsigned)((tot + 255)/256), B), blk>>>((float*)d_out, gp, B, L, N, K);
    (void)out_size;
}

// round 12
// speedup vs baseline: 1.2833x; 1.0586x over previous
#include <cuda_runtime.h>

#define EPSF 1e-9f
#define FMINN 1.17549435e-38f
#define TOPKK 13
#define MAXB 8
#define MAXN 50
#define MAXL 8400
#define MAXK 17
#define CH   25     // gts per K1 z-chunk
#define NCH  2
#define CAP  4096

extern "C" __device__ float __nv_expf(float);
extern "C" __device__ float __nv_powf(float, float);

// ---------------- device scratch ----------------
__device__ float g_align[MAXB*MAXN*MAXL];
__device__ float g_iou  [MAXB*MAXN*MAXL];
__device__ unsigned int       g_gts[NCH][MAXB*MAXL];   // in_gts bits (CH per word)
__device__ unsigned long long g_topk[MAXB*MAXL];       // topk bit n
__device__ float g_cmaxv[NCH][MAXB*MAXL];              // per-chunk iou argmax val
__device__ short g_cmaxi[NCH][MAXB*MAXL];              // per-chunk iou argmax idx
__device__ short         g_coln[MAXB*MAXL];
__device__ unsigned char g_pos [MAXB*MAXL];
__device__ float g_maxm[MAXB*MAXN];
__device__ float g_maxi[MAXB*MAXN];
// K0 per-(b,n[,k]) precompute
__device__ float4 g_kp4 [MAXB*MAXN*MAXK];              // gx, gy, screen-thresh, vis
__device__ float  g_aeps[MAXB*MAXN];
__device__ float  g_areac[MAXB*MAXN];
__device__ float  g_nvise[MAXB*MAXN];

__device__ __forceinline__ float ftz(float x) { return (x < FMINN) ? 0.f : x; }

// ============================================================
// K0: per-gt setup
// ============================================================
__global__ void __launch_bounds__(256)
k0_setup(const float* __restrict__ gb, const float* __restrict__ gp,
         const float* __restrict__ sg, int B, int N, int K)
{
    __shared__ float s_s2[MAXK];
    __shared__ float s_aeps[MAXN];
    const int b = blockIdx.x, tid = threadIdx.x;

    if (tid < K) { float t = __fmul_rn(2.0f, sg[tid]); s_s2[tid] = __fmul_rn(t, t); }
    if (tid < N) {
        int n = tid;
        const float* bx = gb + (b*N + n)*4;
        float wg = __fsub_rn(bx[2], bx[0]), hg = __fsub_rn(bx[3], bx[1]);
        g_areac[b*N + n] = __fmul_rn(fmaxf(wg, 0.f), fmaxf(hg, 0.f));
        float ae = __fadd_rn(__fmul_rn(__fmul_rn(wg, hg), 0.53f), EPSF);
        s_aeps[n] = ae; g_aeps[b*N + n] = ae;
        float c = 0.f;
        for (int k = 0; k < K; k++) {
            float v = gp[((long)(b*N + n)*K + k)*3 + 2];
            c = __fadd_rn(c, (v > 0.f) ? 1.f : 0.f);
        }
        g_nvise[b*N + n] = __fadd_rn(c, EPSF);
    }
    __syncthreads();
    for (int j = tid; j < N*K; j += blockDim.x) {
        int n = j / K, k = j - n*K;
        const float* g = gp + ((long)(b*N + n)*K + k)*3;
        // d > th  =>  e > 87.9  =>  exp term < min-normal => flushed to 0
        double th = (double)s_s2[k] * (double)s_aeps[n] * 2.0 * 87.9;
        g_kp4[(b*N + n)*K + k] = make_float4(g[0], g[1], (float)th, (g[2] > 0.f) ? 1.f : 0.f);
    }
}

// ============================================================
// K1: pairwise metrics (FTZ) + fused per-chunk iou argmax
// ============================================================
__global__ void __launch_bounds__(256)
k1_metrics(const float* __restrict__ ps, const float* __restrict__ pb,
           const float* __restrict__ pp, const float* __restrict__ ap,
           const int*   __restrict__ glab, const float* __restrict__ gb,
           const float* __restrict__ sg,
           int B, int L, int C, int N, int K)
{
    __shared__ float4 s_box[CH];
    __shared__ float4 s_kp [CH*MAXK];
    __shared__ float  s_aeps[CH], s_areac[CH], s_nvise[CH];
    __shared__ int    s_lab[CH];
    __shared__ float  s_s2[MAXK];

    const int b = blockIdx.y, z = blockIdx.z, tid = threadIdx.x;
    const int c0 = z*CH;
    const int cn = min(N, c0 + CH) - c0;

    if (tid < K) { float t = __fmul_rn(2.0f, sg[tid]); s_s2[tid] = __fmul_rn(t, t); }
    if (tid < cn) {
        int n = c0 + tid;
        s_box[tid]   = ((const float4*)gb)[b*N + n];
        s_aeps[tid]  = g_aeps[b*N + n];
        s_areac[tid] = g_areac[b*N + n];
        s_nvise[tid] = g_nvise[b*N + n];
        s_lab[tid]   = glab[b*N + n];
    }
    for (int j = tid; j < cn*K; j += blockDim.x)
        s_kp[j] = g_kp4[(b*N + c0)*K + j];
    __syncthreads();

    const int l = blockIdx.x*blockDim.x + tid;
    if (l >= L) return;

    float4 p = ((const float4*)pb)[b*L + l];
    float area_p = __fmul_rn(fmaxf(__fsub_rn(p.z, p.x), 0.f),
                             fmaxf(__fsub_rn(p.w, p.y), 0.f));
    float axx = ap[l*2], ayy = ap[l*2 + 1];

    float2 kp[MAXK];
    const float2* pprow = (const float2*)(pp + ((long)(b*L + l))*MAXK*2);
    #pragma unroll
    for (int k = 0; k < MAXK; k++) kp[k] = pprow[k];
    const float* psrow = ps + (long)(b*L + l)*C;

    unsigned int bits = 0;
    float amv = -3.402823e38f; int ami = c0;     // chunk iou argmax (first-occurrence)
    for (int j = 0; j < cn; j++) {
        const int n = c0 + j;
        float4 g4 = s_box[j];
        float ox = __fsub_rn(fminf(g4.z, p.z), fmaxf(g4.x, p.x));
        float oy = __fsub_rn(fminf(g4.w, p.w), fmaxf(g4.y, p.y));
        float ov = __fmul_rn(fmaxf(ox, 0.f), fmaxf(oy, 0.f));
        float dmin = fminf(fminf(__fsub_rn(axx, g4.x), __fsub_rn(ayy, g4.y)),
                           fminf(__fsub_rn(g4.z, axx), __fsub_rn(g4.w, ayy)));
        float io2 = 0.f, al = 0.f;
        if (ov > 0.f) {
            float den = __fadd_rn(__fsub_rn(__fadd_rn(s_areac[j], area_p), ov), EPSF);
            float iou = __fdiv_rn(ov, den);
            float aeps = s_aeps[j];
            float s = 0.f;
            #pragma unroll
            for (int k = 0; k < MAXK; k++) {
                float4 kk = s_kp[j*MAXK + k];
                if (kk.w > 0.f) {
                    float dx = __fsub_rn(kk.x, kp[k].x);
                    float dy = __fsub_rn(kk.y, kp[k].y);
                    float d  = __fadd_rn(__fmul_rn(dx, dx), __fmul_rn(dy, dy));
                    if (d <= kk.z) {
                        float e = __fdiv_rn(__fdiv_rn(__fdiv_rn(d, s_s2[k]), aeps), 2.0f);
                        s = __fadd_rn(s, ftz(__nv_expf(-e)));
                    }
                }
            }
            float oks = ftz(__fdiv_rn(s, s_nvise[j]));
            io2 = ftz(__fmul_rn(iou, oks));
            float p6 = ftz(__nv_powf(io2, 6.0f));
            al = ftz(__fmul_rn(psrow[s_lab[j]], p6));
        }
        if (io2 > amv) { amv = io2; ami = n; }   // strict > keeps lowest n
        long idx = ((long)(b*N + n))*L + l;
        g_iou[idx]   = io2;
        g_align[idx] = al;
        if (dmin > EPSF) bits |= (1u << j);
    }
    const int bl = b*L + l;
    g_gts[z][bl]   = bits;
    g_cmaxv[z][bl] = amv;
    g_cmaxi[z][bl] = (short)ami;
    if (z == 0) g_topk[bl] = 0ull;   // reset per replay
}

// ============================================================
// K2: top-13 per (b,n) via candidate collection
// ============================================================
__global__ void __launch_bounds__(256)
k2_topk(const float* __restrict__ pad, int B, int L, int N)
{
    __shared__ float cv[CAP];
    __shared__ int   ci[CAP];
    __shared__ int   cnt;
    __shared__ float rv[256];
    __shared__ int   ri[256];
    __shared__ int   rp[256];

    const int n = blockIdx.x, b = blockIdx.y, tid = threadIdx.x;
    const long row = ((long)(b*N + n))*L;

    if (tid == 0) { g_maxm[b*N + n] = 0.f; g_maxi[b*N + n] = 0.f; cnt = 0; }
    __syncthreads();
    if (pad[b*N + n] <= 0.f) return;

    const int zc = n / CH;
    const unsigned int bit = 1u << (n - zc*CH);
    for (int i = tid; i < L; i += 256) {
        float v = g_align[row + i];
        if (v > 0.f) {
            if (g_gts[zc][b*L + i] & bit) {
                int id = atomicAdd(&cnt, 1);
                if (id < CAP) { cv[id] = v; ci[id] = i; }
            }
        }
    }
    __syncthreads();

    const int c = min(cnt, CAP);
    const unsigned long long nb = 1ull << n;

    if (c <= TOPKK) {
        if (tid < c) atomicOr(&g_topk[(long)b*L + ci[tid]], nb);
        if (tid == 0) {
            int fill = TOPKK - c;
            for (int i = 0; fill > 0; i++) {
                bool cand = false;
                for (int j = 0; j < c; j++) if (ci[j] == i) { cand = true; break; }
                if (!cand) { atomicOr(&g_topk[(long)b*L + i], nb); fill--; }
            }
        }
    } else {
        for (int t = 0; t < TOPKK; t++) {
            float bv = -1.f; int ba = 0x7fffffff; int bp = -1;
            for (int i = tid; i < c; i += 256) {
                float v = cv[i]; int a = ci[i];
                if (v > bv || (v == bv && a < ba)) { bv = v; ba = a; bp = i; }
            }
            rv[tid] = bv; ri[tid] = ba; rp[tid] = bp;
            __syncthreads();
            for (int off = 128; off > 0; off >>= 1) {
                if (tid < off) {
                    float v2 = rv[tid+off]; int a2 = ri[tid+off];
                    if (v2 > rv[tid] || (v2 == rv[tid] && a2 < ri[tid])) {
                        rv[tid] = v2; ri[tid] = a2; rp[tid] = rp[tid+off];
                    }
                }
                __syncthreads();
            }
            if (tid == 0) {
                atomicOr(&g_topk[(long)b*L + ri[0]], nb);
                cv[rp[0]] = -1.f;
            }
            __syncthreads();
        }
    }
}

// ============================================================
// K3: per-anchor resolve — bit ops + 2-way chunk-argmax combine
// ============================================================
__global__ void __launch_bounds__(256)
k3_resolve(int B, int L, int N)
{
    const int l = blockIdx.x*blockDim.x + threadIdx.x;
    const int b = blockIdx.y;
    if (l >= L) return;
    const int bl = b*L + l;

    unsigned long long gts = (unsigned long long)g_gts[0][bl]
                           | ((unsigned long long)g_gts[1][bl] << CH);
    unsigned long long pos64 = gts & g_topk[bl];
    int cnt = __popcll(pos64);

    int asg = 0, pos = 0;
    if (cnt == 1) { asg = __ffsll((long long)pos64) - 1; pos = 1; }
    else if (cnt > 1) {                 // global iou argmax, first-occurrence ties
        float v0 = g_cmaxv[0][bl], v1 = g_cmaxv[1][bl];
        asg = (v1 > v0) ? (int)g_cmaxi[1][bl] : (int)g_cmaxi[0][bl];
        pos = 1;
    }
    g_coln[bl] = (short)asg;
    g_pos [bl] = (unsigned char)pos;
    if (pos) {
        long idx = ((long)(b*N + asg))*L + l;
        atomicMax((int*)&g_maxm[b*N + asg], __float_as_int(g_align[idx]));
        atomicMax((int*)&g_maxi[b*N + asg], __float_as_int(g_iou[idx]));
    }
}

// ============================================================
// K5: scalar outputs + bboxes (gt tables staged in smem)
// layout: [labels BL][bboxes 4BL][poses 3K*BL][scores C*BL][gtidx BL][crowd BL]
// ============================================================
__global__ void __launch_bounds__(256)
k5_out(float* __restrict__ out,
       const int* __restrict__ glab, const float* __restrict__ gb,
       const int* __restrict__ gcrowd, const int* __restrict__ bgp,
       int B, int L, int C, int N, int K)
{
    __shared__ int    s_lab[MAXN], s_crowd[MAXN];
    __shared__ float4 s_box[MAXN];
    __shared__ float  s_mm[MAXN], s_mi[MAXN];

    const int b = blockIdx.y, tid = threadIdx.x;
    if (tid < N) {
        s_lab[tid]   = glab[b*N + tid];
        s_crowd[tid] = gcrowd[b*N + tid];
        s_box[tid]   = ((const float4*)gb)[b*N + tid];
        s_mm[tid]    = g_maxm[b*N + tid];
        s_mi[tid]    = g_maxi[b*N + tid];
    }
    __syncthreads();

    const int l = blockIdx.x*blockDim.x + tid;
    if (l >= L) return;
    const int bg = bgp ? bgp[0] : 1;

    const int n     = g_coln[b*L + l];
    const int pos   = g_pos [b*L + l];
    const int crowd = s_crowd[n];

    const int lab_pre = pos ? s_lab[n] : bg;
    const int lab_fin = (crowd > 0) ? bg : lab_pre;

    float mult = 0.f;
    if (pos) {
        long idx = ((long)(b*N + n))*L + l;
        mult = __fmul_rn(__fdiv_rn(g_align[idx], __fadd_rn(s_mm[n], EPSF)), s_mi[n]);
    }
    const float cf = (crowd < 1) ? 1.f : 0.f;

    const long BL = (long)B*L;
    const long o  = (long)b*L + l;

    out[o] = (float)lab_fin;
    ((float4*)(out + BL))[o] = s_box[n];

    const long off_sc = BL*5 + BL*(long)K*3;
    for (int cc = 0; cc < C; cc++) {
        int kept = (cc < bg) ? cc : cc + 1;
        out[off_sc + o*C + cc] = __fmul_rn((lab_pre == kept) ? mult : 0.f, cf);
    }
    const long off_gi = off_sc + BL*(long)C;
    out[off_gi + o]      = (float)(n + b*N);
    out[off_gi + BL + o] = (crowd > 0) ? 1.f : 0.f;
}

// ============================================================
// K6: pose gather — gt poses staged in smem, coalesced writes
// ============================================================
__global__ void __launch_bounds__(256)
k6_poses(float* __restrict__ out, const float* __restrict__ gp,
         int B, int L, int N, int K)
{
    __shared__ float s_gp[MAXN*MAXK*3];
    const int b = blockIdx.y, tid = threadIdx.x;
    const int K3 = K*3;
    for (int j = tid; j < N*K3; j += 256) s_gp[j] = gp[(long)b*N*K3 + j];
    __syncthreads();

    const long i = (long)blockIdx.x*256 + tid;
    if (i >= (long)L*K3) return;
    const int l = (int)(i / K3);
    const int j = (int)(i - (long)l*K3);
    const int n = g_coln[b*L + l];
    out[(long)B*L*5 + (long)b*L*K3 + i] = s_gp[n*K3 + j];
}

// ============================================================
extern "C" void kernel_launch(void* const* d_in, const int* in_sizes, int n_in,
                              void* d_out, int out_size)
{
    const float* ps   = (const float*)d_in[0];
    const float* pb   = (const float*)d_in[1];
    const float* pp   = (const float*)d_in[2];
    const float* ap   = (const float*)d_in[3];
    const int*   glab = (const int*)  d_in[4];
    const float* gb   = (const float*)d_in[5];
    const float* gp   = (const float*)d_in[6];
    const int*   gc   = (const int*)  d_in[7];
    const float* pad  = (const float*)d_in[8];
    const float* sg   = (const float*)d_in[9];
    const int*   bgp  = (n_in > 10) ? (const int*)d_in[10] : nullptr;

    const int K  = in_sizes[9];
    const int L  = in_sizes[3] / 2;
    const int BL = in_sizes[1] / 4;
    const int B  = BL / L;
    const int C  = in_sizes[0] / BL;
    const int N  = in_sizes[4] / B;

    dim3 blk(256);
    const int gx = (L + 255)/256;
    k0_setup  <<<B, blk>>>(gb, gp, sg, B, N, K);
    k1_metrics<<<dim3(gx, B, NCH), blk>>>(ps, pb, pp, ap, glab, gb, sg, B, L, C, N, K);
    k2_topk   <<<dim3(N, B), blk>>>(pad, B, L, N);
    k3_resolve<<<dim3(gx, B), blk>>>(B, L, N);
    k5_out    <<<dim3(gx, B), blk>>>((float*)d_out, glab, gb, gc, bgp, B, L, C, N, K);
    const long tot = (long)L*K*3;
    k6_poses  <<<dim3((unsigned)((tot + 255)/256), B), blk>>>((float*)d_out, gp, B, L, N, K);
    (void)out_size;
}

// round 13
// speedup vs baseline: 2.5653x; 1.9990x over previous
#include <cuda_runtime.h>

#define EPSF 1e-9f
#define FMINN 1.17549435e-38f
#define TOPKK 13
#define MAXB 8
#define MAXN 50
#define MAXL 8400
#define MAXK 17
#define CH   25      // gts per K1 z-chunk
#define NCH  2
#define CAPC 2048    // per-gt candidate list capacity

extern "C" __device__ float __nv_expf(float);
extern "C" __device__ float __nv_powf(float, float);

// ---------------- device scratch ----------------
__device__ float g_align[MAXB*MAXN*MAXL];
__device__ float g_iou  [MAXB*MAXN*MAXL];
__device__ unsigned int       g_gts[NCH][MAXB*MAXL];
__device__ unsigned long long g_topk[MAXB*MAXL];
__device__ float g_cmaxv[NCH][MAXB*MAXL];
__device__ short g_cmaxi[NCH][MAXB*MAXL];
__device__ short         g_coln[MAXB*MAXL];
__device__ unsigned char g_pos [MAXB*MAXL];
__device__ float g_maxm[MAXB*MAXN];
__device__ float g_maxi[MAXB*MAXN];
__device__ int   g_ccnt[MAXB*MAXN];
__device__ float g_cv[MAXB*MAXN*CAPC];
__device__ int   g_cl[MAXB*MAXN*CAPC];
// K0 per-(b,n[,k]) precompute
__device__ float4 g_kp4 [MAXB*MAXN*MAXK];   // gx, gy, screen-thresh, vis
__device__ float  g_aeps[MAXB*MAXN];
__device__ float  g_areac[MAXB*MAXN];
__device__ float  g_nvise[MAXB*MAXN];

__device__ __forceinline__ float ftz(float x) { return (x < FMINN) ? 0.f : x; }

// ============================================================
// K0: per-gt setup + counter reset
// ============================================================
__global__ void __launch_bounds__(256)
k0_setup(const float* __restrict__ gb, const float* __restrict__ gp,
         const float* __restrict__ sg, int B, int N, int K)
{
    __shared__ float s_s2[MAXK];
    __shared__ float s_aeps[MAXN];
    const int b = blockIdx.x, tid = threadIdx.x;

    if (tid < K) { float t = __fmul_rn(2.0f, sg[tid]); s_s2[tid] = __fmul_rn(t, t); }
    if (tid < N) {
        int n = tid;
        g_ccnt[b*N + n] = 0;
        const float* bx = gb + (b*N + n)*4;
        float wg = __fsub_rn(bx[2], bx[0]), hg = __fsub_rn(bx[3], bx[1]);
        g_areac[b*N + n] = __fmul_rn(fmaxf(wg, 0.f), fmaxf(hg, 0.f));
        float ae = __fadd_rn(__fmul_rn(__fmul_rn(wg, hg), 0.53f), EPSF);
        s_aeps[n] = ae; g_aeps[b*N + n] = ae;
        float c = 0.f;
        for (int k = 0; k < K; k++) {
            float v = gp[((long)(b*N + n)*K + k)*3 + 2];
            c = __fadd_rn(c, (v > 0.f) ? 1.f : 0.f);
        }
        g_nvise[b*N + n] = __fadd_rn(c, EPSF);
    }
    __syncthreads();
    for (int j = tid; j < N*K; j += blockDim.x) {
        int n = j / K, k = j - n*K;
        const float* g = gp + ((long)(b*N + n)*K + k)*3;
        // d > th  =>  e > 87.9  =>  exp term < min-normal => flushed to 0
        double th = (double)s_s2[k] * (double)s_aeps[n] * 2.0 * 87.9;
        g_kp4[(b*N + n)*K + k] = make_float4(g[0], g[1], (float)th, (g[2] > 0.f) ? 1.f : 0.f);
    }
}

// ============================================================
// K1: phase A (cheap screen + zero fill) -> smem pair queue ->
//     phase B (full-efficiency heavy math) ; FTZ pipeline
// ============================================================
__global__ void __launch_bounds__(256)
k1_metrics(const float* __restrict__ ps, const float* __restrict__ pb,
           const float* __restrict__ pp, const float* __restrict__ ap,
           const int*   __restrict__ glab, const float* __restrict__ gb,
           const float* __restrict__ sg,
           int B, int L, int C, int N, int K)
{
    __shared__ float4 s_box[CH];
    __shared__ float4 s_kp [CH*MAXK];
    __shared__ float  s_aeps[CH], s_areac[CH], s_nvise[CH];
    __shared__ int    s_lab[CH];
    __shared__ float  s_s2[MAXK];
    __shared__ unsigned int s_bits[256];
    __shared__ unsigned long long s_amax[256];
    __shared__ unsigned int s_q[CH*256];
    __shared__ int s_qc;

    const int b = blockIdx.y, z = blockIdx.z, tid = threadIdx.x;
    const int c0 = z*CH;
    const int cn = min(N, c0 + CH) - c0;

    if (tid == 0) s_qc = 0;
    if (tid < K) { float t = __fmul_rn(2.0f, sg[tid]); s_s2[tid] = __fmul_rn(t, t); }
    if (tid < cn) {
        int n = c0 + tid;
        s_box[tid]   = ((const float4*)gb)[b*N + n];
        s_aeps[tid]  = g_aeps[b*N + n];
        s_areac[tid] = g_areac[b*N + n];
        s_nvise[tid] = g_nvise[b*N + n];
        s_lab[tid]   = glab[b*N + n];
    }
    for (int j = tid; j < cn*K; j += blockDim.x)
        s_kp[j] = g_kp4[(b*N + c0)*K + j];
    __syncthreads();

    const int l = blockIdx.x*blockDim.x + tid;
    const bool active = (l < L);

    if (active) {
        float4 p = ((const float4*)pb)[b*L + l];
        float axx = ap[l*2], ayy = ap[l*2 + 1];
        unsigned int bits = 0;
        for (int j = 0; j < cn; j++) {
            float4 g4 = s_box[j];
            float ox = __fsub_rn(fminf(g4.z, p.z), fmaxf(g4.x, p.x));
            float oy = __fsub_rn(fminf(g4.w, p.w), fmaxf(g4.y, p.y));
            float ov = __fmul_rn(fmaxf(ox, 0.f), fmaxf(oy, 0.f));
            float dmin = fminf(fminf(__fsub_rn(axx, g4.x), __fsub_rn(ayy, g4.y)),
                               fminf(__fsub_rn(g4.z, axx), __fsub_rn(g4.w, ayy)));
            long idx = ((long)(b*N + c0 + j))*L + l;
            g_iou[idx]   = 0.f;
            g_align[idx] = 0.f;
            if (dmin > EPSF) bits |= (1u << j);
            if (ov > 0.f) {
                int qp = atomicAdd(&s_qc, 1);
                s_q[qp] = ((unsigned)tid << 5) | (unsigned)j;
            }
        }
        s_bits[tid] = bits;
        // init argmax key: io2 = 0 at n = c0 (first occurrence over all-zero row)
        s_amax[tid] = (unsigned long long)(unsigned)(N - c0);
        g_gts[z][b*L + l] = bits;
        if (z == 0) g_topk[b*L + l] = 0ull;
    }
    __syncthreads();

    const int qc = s_qc;
    for (int q = tid; q < qc; q += 256) {
        unsigned e = s_q[q];
        int ll = (int)(e >> 5), j = (int)(e & 31);
        int lg = blockIdx.x*256 + ll;
        int n  = c0 + j;
        float4 p = ((const float4*)pb)[b*L + lg];
        float area_p = __fmul_rn(fmaxf(__fsub_rn(p.z, p.x), 0.f),
                                 fmaxf(__fsub_rn(p.w, p.y), 0.f));
        float4 g4 = s_box[j];
        float ox = __fsub_rn(fminf(g4.z, p.z), fmaxf(g4.x, p.x));
        float oy = __fsub_rn(fminf(g4.w, p.w), fmaxf(g4.y, p.y));
        float ov = __fmul_rn(fmaxf(ox, 0.f), fmaxf(oy, 0.f));
        float den = __fadd_rn(__fsub_rn(__fadd_rn(s_areac[j], area_p), ov), EPSF);
        float iou = __fdiv_rn(ov, den);
        float aeps = s_aeps[j];
        const float2* pr = (const float2*)(pp + ((long)(b*L + lg))*MAXK*2);
        float s = 0.f;
        #pragma unroll
        for (int k = 0; k < MAXK; k++) {
            float4 kk = s_kp[j*MAXK + k];
            if (kk.w > 0.f) {
                float2 q2 = pr[k];
                float dx = __fsub_rn(kk.x, q2.x);
                float dy = __fsub_rn(kk.y, q2.y);
                float d  = __fadd_rn(__fmul_rn(dx, dx), __fmul_rn(dy, dy));
                if (d <= kk.z) {
                    float e2 = __fdiv_rn(__fdiv_rn(__fdiv_rn(d, s_s2[k]), aeps), 2.0f);
                    s = __fadd_rn(s, ftz(__nv_expf(-e2)));
                }
            }
        }
        float oks = ftz(__fdiv_rn(s, s_nvise[j]));
        float io2 = ftz(__fmul_rn(iou, oks));
        float p6  = ftz(__nv_powf(io2, 6.0f));
        float al  = ftz(__fmul_rn(ps[(long)(b*L + lg)*C + s_lab[j]], p6));

        long idx = ((long)(b*N + n))*L + lg;
        g_iou[idx]   = io2;
        g_align[idx] = al;
        unsigned long long key =
            ((unsigned long long)__float_as_uint(io2) << 32) | (unsigned)(N - n);
        atomicMax(&s_amax[ll], key);
        if (al > 0.f && ((s_bits[ll] >> j) & 1u)) {
            int id = atomicAdd(&g_ccnt[b*N + n], 1);
            if (id < CAPC) {
                g_cv[(b*N + n)*CAPC + id] = al;
                g_cl[(b*N + n)*CAPC + id] = lg;
            }
        }
    }
    __syncthreads();

    if (active) {
        unsigned long long key = s_amax[tid];
        g_cmaxv[z][b*L + l] = __uint_as_float((unsigned)(key >> 32));
        g_cmaxi[z][b*L + l] = (short)(N - (int)(key & 0xffffffffull));
    }
}

// ============================================================
// K2: top-13 per (b,n) from candidate lists (fallback: full scan)
// ============================================================
__global__ void __launch_bounds__(256)
k2_topk(const float* __restrict__ pad, int B, int L, int N)
{
    __shared__ float cv[CAPC];
    __shared__ int   ci[CAPC];
    __shared__ float rv[256];
    __shared__ int   ri[256];
    __shared__ int   rp[256];
    __shared__ int   sel[TOPKK];

    const int n = blockIdx.x, b = blockIdx.y, tid = threadIdx.x;

    if (tid == 0) { g_maxm[b*N + n] = 0.f; g_maxi[b*N + n] = 0.f; }
    if (pad[b*N + n] <= 0.f) return;

    const int cnt = g_ccnt[b*N + n];
    const unsigned long long nb = 1ull << n;

    if (cnt <= CAPC) {
        for (int i = tid; i < cnt; i += 256) {
            cv[i] = g_cv[(b*N + n)*CAPC + i];
            ci[i] = g_cl[(b*N + n)*CAPC + i];
        }
        __syncthreads();
        if (cnt <= TOPKK) {
            if (tid < cnt) atomicOr(&g_topk[(long)b*L + ci[tid]], nb);
            if (tid == 0) {
                int fill = TOPKK - cnt;
                for (int i = 0; fill > 0; i++) {
                    bool cand = false;
                    for (int j = 0; j < cnt; j++) if (ci[j] == i) { cand = true; break; }
                    if (!cand) { atomicOr(&g_topk[(long)b*L + i], nb); fill--; }
                }
            }
        } else {
            for (int t = 0; t < TOPKK; t++) {
                float bv = -1.f; int ba = 0x7fffffff; int bp = -1;
                for (int i = tid; i < cnt; i += 256) {
                    float v = cv[i]; int a = ci[i];
                    if (v > bv || (v == bv && a < ba)) { bv = v; ba = a; bp = i; }
                }
                rv[tid] = bv; ri[tid] = ba; rp[tid] = bp;
                __syncthreads();
                for (int off = 128; off > 0; off >>= 1) {
                    if (tid < off) {
                        float v2 = rv[tid+off]; int a2 = ri[tid+off];
                        if (v2 > rv[tid] || (v2 == rv[tid] && a2 < ri[tid])) {
                            rv[tid] = v2; ri[tid] = a2; rp[tid] = rp[tid+off];
                        }
                    }
                    __syncthreads();
                }
                if (tid == 0) { atomicOr(&g_topk[(long)b*L + ri[0]], nb); cv[rp[0]] = -1.f; }
                __syncthreads();
            }
        }
    } else {
        // fallback: 13 full-row selection passes (value desc, index asc),
        // masked by in_gts; previously selected indices excluded via sel[].
        const long row = ((long)(b*N + n))*L;
        const int zc = n / CH;
        const unsigned int bit = 1u << (n - zc*CH);
        for (int t = 0; t < TOPKK; t++) {
            float bv = -1.f; int ba = 0x7fffffff;
            for (int i = tid; i < L; i += 256) {
                bool skip = false;
                for (int u = 0; u < t; u++) if (sel[u] == i) { skip = true; break; }
                if (skip) continue;
                float v = (g_gts[zc][b*L + i] & bit) ? g_align[row + i] : 0.f;
                if (v > bv) { bv = v; ba = i; }
            }
            rv[tid] = bv; ri[tid] = ba;
            __syncthreads();
            for (int off = 128; off > 0; off >>= 1) {
                if (tid < off) {
                    float v2 = rv[tid+off]; int a2 = ri[tid+off];
                    if (v2 > rv[tid] || (v2 == rv[tid] && a2 < ri[tid])) { rv[tid] = v2; ri[tid] = a2; }
                }
                __syncthreads();
            }
            if (tid == 0) { sel[t] = ri[0]; atomicOr(&g_topk[(long)b*L + ri[0]], nb); }
            __syncthreads();
        }
    }
}

// ============================================================
// K3: per-anchor resolve — bit ops + 2-way chunk-argmax combine
// ============================================================
__global__ void __launch_bounds__(256)
k3_resolve(int B, int L, int N)
{
    const int l = blockIdx.x*blockDim.x + threadIdx.x;
    const int b = blockIdx.y;
    if (l >= L) return;
    const int bl = b*L + l;

    unsigned long long gts = (unsigned long long)g_gts[0][bl]
                           | ((unsigned long long)g_gts[1][bl] << CH);
    unsigned long long pos64 = gts & g_topk[bl];
    int cnt = __popcll(pos64);

    int asg = 0, pos = 0;
    if (cnt == 1) { asg = __ffsll((long long)pos64) - 1; pos = 1; }
    else if (cnt > 1) {
        float v0 = g_cmaxv[0][bl], v1 = g_cmaxv[1][bl];
        asg = (v1 > v0) ? (int)g_cmaxi[1][bl] : (int)g_cmaxi[0][bl];
        pos = 1;
    }
    g_coln[bl] = (short)asg;
    g_pos [bl] = (unsigned char)pos;
    if (pos) {
        long idx = ((long)(b*N + asg))*L + l;
        atomicMax((int*)&g_maxm[b*N + asg], __float_as_int(g_align[idx]));
        atomicMax((int*)&g_maxi[b*N + asg], __float_as_int(g_iou[idx]));
    }
}

// ============================================================
// K56: fused outputs — labels/bboxes/scores/gtidx/crowd + poses
// layout: [labels BL][bboxes 4BL][poses 3K*BL][scores C*BL][gtidx BL][crowd BL]
// ============================================================
__global__ void __launch_bounds__(256)
k56_out(float* __restrict__ out,
        const int* __restrict__ glab, const float* __restrict__ gb,
        const int* __restrict__ gcrowd, const int* __restrict__ bgp,
        const float* __restrict__ gp,
        int B, int L, int C, int N, int K)
{
    __shared__ int    s_lab[MAXN], s_crowd[MAXN];
    __shared__ float4 s_box[MAXN];
    __shared__ float  s_mm[MAXN], s_mi[MAXN];
    __shared__ float  s_gp[MAXN*MAXK*3];

    const int b = blockIdx.y, tid = threadIdx.x;
    const int K3 = K*3;
    if (tid < N) {
        s_lab[tid]   = glab[b*N + tid];
        s_crowd[tid] = gcrowd[b*N + tid];
        s_box[tid]   = ((const float4*)gb)[b*N + tid];
        s_mm[tid]    = g_maxm[b*N + tid];
        s_mi[tid]    = g_maxi[b*N + tid];
    }
    for (int j = tid; j < N*K3; j += 256) s_gp[j] = gp[(long)b*N*K3 + j];
    __syncthreads();

    const int l = blockIdx.x*blockDim.x + tid;
    if (l >= L) return;
    const int bg = bgp ? bgp[0] : 1;

    const int n     = g_coln[b*L + l];
    const int pos   = g_pos [b*L + l];
    const int crowd = s_crowd[n];

    const int lab_pre = pos ? s_lab[n] : bg;
    const int lab_fin = (crowd > 0) ? bg : lab_pre;

    float mult = 0.f;
    if (pos) {
        long idx = ((long)(b*N + n))*L + l;
        mult = __fmul_rn(__fdiv_rn(g_align[idx], __fadd_rn(s_mm[n], EPSF)), s_mi[n]);
    }
    const float cf = (crowd < 1) ? 1.f : 0.f;

    const long BL = (long)B*L;
    const long o  = (long)b*L + l;

    out[o] = (float)lab_fin;
    ((float4*)(out + BL))[o] = s_box[n];

    float* pout = out + BL*5 + (long)b*L*K3 + (long)l*K3;
    const float* src = s_gp + n*K3;
    #pragma unroll
    for (int j = 0; j < MAXK*3; j++) pout[j] = src[j];

    const long off_sc = BL*5 + BL*(long)K*3;
    for (int cc = 0; cc < C; cc++) {
        int kept = (cc < bg) ? cc : cc + 1;
        out[off_sc + o*C + cc] = __fmul_rn((lab_pre == kept) ? mult : 0.f, cf);
    }
    const long off_gi = off_sc + BL*(long)C;
    out[off_gi + o]      = (float)(n + b*N);
    out[off_gi + BL + o] = (crowd > 0) ? 1.f : 0.f;
}

// ============================================================
extern "C" void kernel_launch(void* const* d_in, const int* in_sizes, int n_in,
                              void* d_out, int out_size)
{
    const float* ps   = (const float*)d_in[0];
    const float* pb   = (const float*)d_in[1];
    const float* pp   = (const float*)d_in[2];
    const float* ap   = (const float*)d_in[3];
    const int*   glab = (const int*)  d_in[4];
    const float* gb   = (const float*)d_in[5];
    const float* gp   = (const float*)d_in[6];
    const int*   gc   = (const int*)  d_in[7];
    const float* pad  = (const float*)d_in[8];
    const float* sg   = (const float*)d_in[9];
    const int*   bgp  = (n_in > 10) ? (const int*)d_in[10] : nullptr;

    const int K  = in_sizes[9];
    const int L  = in_sizes[3] / 2;
    const int BL = in_sizes[1] / 4;
    const int B  = BL / L;
    const int C  = in_sizes[0] / BL;
    const int N  = in_sizes[4] / B;

    dim3 blk(256);
    const int gx = (L + 255)/256;
    k0_setup  <<<B, blk>>>(gb, gp, sg, B, N, K);
    k1_metrics<<<dim3(gx, B, NCH), blk>>>(ps, pb, pp, ap, glab, gb, sg, B, L, C, N, K);
    k2_topk   <<<dim3(N, B), blk>>>(pad, B, L, N);
    k3_resolve<<<dim3(gx, B), blk>>>(B, L, N);
    k56_out   <<<dim3(gx, B), blk>>>((float*)d_out, glab, gb, gc, bgp, gp, B, L, C, N, K);
    (void)out_size;
}